// round 14
// baseline (speedup 1.0000x reference)
#include <cuda_runtime.h>
#include <cuda_fp16.h>
#include <cstdint>

// ============================================================================
// Gps, fp16 single-term mma.sync m16n8k16 (validated rel_err 4.400397e-4).
// R14: launch1 fusion reverted (fold-with-G1 contention cost >100us).
//   L1: unified prep (tconv f1, tconv f2, wconv W1/W2, gather) — one launch
//   L2: fold4cvt full-chip streaming (adj2 4-row sums -> fp16)
//   L3: G1 fused fp32-A GEMM, now with 3-stage B pipeline
//   L4: G2 || G3 in one 512-block launch
//   L5: G4
// All math bit-identical to R12/R13.
// ============================================================================

#define ASTG 18432               // F: A stage 128 x 144B
#define OFFB 36864               // F: B stages at 36864 + st*18432 (3 stages)
#define SMEM_F (36864 + 3 * 18432)   // 92160 -> 2 CTAs/SM
#define PSTG 36864               // P: stage = A 18432 + B 18432
#define SMEM_P (3 * 36864)       // 110592
#define LDW 36
#define NFOLD 1184               // fold grid (full chip, grid-stride)

__device__ __half g_A2h[16384 * 2048];
__device__ __half g_Acat1[16384 * 512];
__device__ __half g_Acat2[16384 * 512];
__device__ __half g_f1h[256 * 4096];
__device__ __half g_f2h[256 * 2048];
__device__ __half g_Wh[2][256 * 512];

__device__ __forceinline__ uint32_t smem_u32(const void* p) {
    uint32_t a;
    asm("{ .reg .u64 t; cvta.to.shared.u64 t, %1; cvt.u32.u64 %0, t; }" : "=r"(a) : "l"(p));
    return a;
}
__device__ __forceinline__ void cpa16(uint32_t dst, const void* src) {
    asm volatile("cp.async.cg.shared.global [%0], [%1], 16;" :: "r"(dst), "l"(src));
}
__device__ __forceinline__ uint32_t pk(__half a, __half b) {
    __half2 t; t.x = a; t.y = b;
    return *(uint32_t*)&t;
}
__device__ __forceinline__ void mma_f16(float* c, const uint32_t* a, const uint32_t* b) {
    asm volatile(
        "mma.sync.aligned.m16n8k16.row.col.f32.f16.f16.f32 "
        "{%0,%1,%2,%3}, {%4,%5,%6,%7}, {%8,%9}, {%0,%1,%2,%3};"
        : "+f"(c[0]), "+f"(c[1]), "+f"(c[2]), "+f"(c[3])
        : "r"(a[0]), "r"(a[1]), "r"(a[2]), "r"(a[3]), "r"(b[0]), "r"(b[1]));
}

// ---------------------------------------------------------------------------
// G1: C_half[16384, 256 @ ldc 512] = fp16(0.5 * A_fp32[16384,4096] @ B^T)
// A: fused fp32 LDG -> cvt -> STS, 2 stages, reg double-buffer in 2 batches.
// B: cp.async, 3 stages (prefetch distance 2 chunks).
// ---------------------------------------------------------------------------
__global__ void __launch_bounds__(256, 2)
gemm_f(const float* __restrict__ A, const __half* __restrict__ B,
       __half* __restrict__ C) {
    extern __shared__ char smem[];
    const uint32_t sb = smem_u32(smem);
    const int tid = threadIdx.x;
    const int l = tid & 31, wid = tid >> 5;
    const int wm = wid & 1, wn = wid >> 1;
    const int bn = blockIdx.x, bm = blockIdx.y;
    const int NK = 64;

    float acc[4][4][4];
#pragma unroll
    for (int mt = 0; mt < 4; mt++)
#pragma unroll
        for (int nt = 0; nt < 4; nt++)
#pragma unroll
            for (int i = 0; i < 4; i++) acc[mt][nt][i] = 0.f;

    const int rbase = tid >> 4;
    const int kq = (tid & 15) << 2;

    auto ldgA = [&](int kc, int hb, float4* r) {
#pragma unroll
        for (int j = 0; j < 4; j++) {
            const int row = rbase + 16 * (hb * 4 + j);
            r[j] = *(const float4*)(A + (size_t)(bm * 128 + row) * 4096 +
                                    (kc << 6) + kq);
        }
    };
    auto stsA = [&](const float4* r, int hb, int s) {
        char* base = smem + s * ASTG;
        const int q = tid & 15;
#pragma unroll
        for (int j = 0; j < 4; j++) {
            const int row = rbase + 16 * (hb * 4 + j);
            uint2 h;
            h.x = pk(__float2half(r[j].x), __float2half(r[j].y));
            h.y = pk(__float2half(r[j].z), __float2half(r[j].w));
            *(uint2*)(base + row * 144 + q * 8) = h;
        }
    };
    auto fillB = [&](int kc, int st) {
#pragma unroll
        for (int j = 0; j < 4; j++) {
            const int g = tid + j * 256;
            const int row = g >> 3, q = g & 7;
            cpa16(sb + OFFB + st * ASTG + row * 144 + q * 16,
                  B + (size_t)(bn * 128 + row) * 4096 + (kc << 6) + q * 8);
        }
        asm volatile("cp.async.commit_group;" ::: "memory");
    };

    // prologue: B stages 0,1 in flight; A chunk 0 in stage 0
    fillB(0, 0);
    fillB(1, 1);
    {
        float4 a0[4];
        ldgA(0, 0, a0); stsA(a0, 0, 0);
        ldgA(0, 1, a0); stsA(a0, 1, 0);
    }

    int stB = 0, stF = 2;
    for (int k = 0; k < NK; k++) {
        const int sA = k & 1;
        if (k < NK - 1) asm volatile("cp.async.wait_group 1;" ::: "memory");
        else            asm volatile("cp.async.wait_group 0;" ::: "memory");
        __syncthreads();   // B(k) + A(k) visible; A stage sA^1, B stage stF free

        if (k + 2 < NK) fillB(k + 2, stF);
        float4 ar[4];
        if (k + 1 < NK) ldgA(k + 1, 0, ar);

        const uint32_t* Ah = (const uint32_t*)(smem + sA * ASTG);
        const uint32_t* Bh = (const uint32_t*)(smem + OFFB + stB * ASTG);
#pragma unroll
        for (int half = 0; half < 2; half++) {
#pragma unroll
            for (int ki = 0; ki < 2; ki++) {
                const int ks = half * 2 + ki;
                const int kw = ks * 8 + (l & 3);
                uint32_t a[4][4];
#pragma unroll
                for (int mt = 0; mt < 4; mt++) {
                    const int r = wm * 64 + mt * 16 + (l >> 2);
                    a[mt][0] = Ah[r * LDW + kw];
                    a[mt][1] = Ah[(r + 8) * LDW + kw];
                    a[mt][2] = Ah[r * LDW + kw + 4];
                    a[mt][3] = Ah[(r + 8) * LDW + kw + 4];
                }
#pragma unroll
                for (int nt = 0; nt < 4; nt++) {
                    const int n = wn * 32 + nt * 8 + (l >> 2);
                    uint32_t b[2];
                    b[0] = Bh[n * LDW + kw];
                    b[1] = Bh[n * LDW + kw + 4];
#pragma unroll
                    for (int mt = 0; mt < 4; mt++) mma_f16(acc[mt][nt], a[mt], b);
                }
            }
            if (k + 1 < NK) {
                stsA(ar, half, sA ^ 1);
                if (half == 0) ldgA(k + 1, 1, ar);
            }
        }
        stB++; if (stB == 3) stB = 0;
        stF++; if (stF == 3) stF = 0;
    }

#pragma unroll
    for (int mt = 0; mt < 4; mt++) {
        const int r0 = bm * 128 + wm * 64 + mt * 16 + (l >> 2);
#pragma unroll
        for (int nt = 0; nt < 4; nt++) {
            const int c0 = bn * 128 + wn * 32 + nt * 8 + 2 * (l & 3);
#pragma unroll
            for (int h = 0; h < 2; h++) {
                const float vx = acc[mt][nt][2 * h + 0] * 0.5f;
                const float vy = acc[mt][nt][2 * h + 1] * 0.5f;
                *(uint32_t*)(C + (size_t)(r0 + h * 8) * 512 + c0) =
                    pk(__float2half(vx), __float2half(vy));
            }
        }
    }
}

// ---------------------------------------------------------------------------
// fold4cvt: A2h[m][k] = fp16(sum_{i<4} adj2[4m+i][k]); full-chip grid-stride,
// 4-way ILP (16 independent LDG.128 in flight per thread).
// ---------------------------------------------------------------------------
__global__ void __launch_bounds__(256)
fold4cvt(const float* __restrict__ in, __half* __restrict__ out) {
    const int T = NFOLD * 256;
    const int idx = blockIdx.x * 256 + threadIdx.x;
    const int NJ = 16384 * 512;                      // uint2 output granules
    for (int j0 = idx; j0 < NJ; j0 += 4 * T) {
        float4 v[4][4];
        int jj[4];
#pragma unroll
        for (int u = 0; u < 4; u++) {
            jj[u] = j0 + u * T;
            if (jj[u] < NJ) {
                const int m = jj[u] >> 9, k4 = (jj[u] & 511) << 2;
                const float* p = in + (size_t)m * 4 * 2048 + k4;
                v[u][0] = *(const float4*)p;
                v[u][1] = *(const float4*)(p + 2048);
                v[u][2] = *(const float4*)(p + 4096);
                v[u][3] = *(const float4*)(p + 6144);
            }
        }
#pragma unroll
        for (int u = 0; u < 4; u++) {
            if (jj[u] < NJ) {
                const int m = jj[u] >> 9, k4 = (jj[u] & 511) << 2;
                uint2 h;
                h.x = pk(__float2half((v[u][0].x + v[u][1].x) + (v[u][2].x + v[u][3].x)),
                         __float2half((v[u][0].y + v[u][1].y) + (v[u][2].y + v[u][3].y)));
                h.y = pk(__float2half((v[u][0].z + v[u][1].z) + (v[u][2].z + v[u][3].z)),
                         __float2half((v[u][0].w + v[u][1].w) + (v[u][2].w + v[u][3].w)));
                *(uint2*)(out + (size_t)m * 2048 + k4) = h;
            }
        }
    }
}

// ---------------------------------------------------------------------------
// P body: pure-fp16 GEMM, both operands cp.async, 3 stages, K-chunk 64.
// ---------------------------------------------------------------------------
struct PD {
    const __half* A; const __half* B; void* C;
    int K; float scale; int lrelu; int ldc;
};

template <int EPIH>
__device__ __forceinline__ void gemm_p_body(const PD d, int bidx, char* smem) {
    const uint32_t sb = smem_u32(smem);
    const int tid = threadIdx.x;
    const int l = tid & 31, wid = tid >> 5;
    const int wm = wid & 1, wn = wid >> 1;
    const int bn = bidx & 1, bm = bidx >> 1;
    const int NK = d.K >> 6;

    float acc[4][4][4];
#pragma unroll
    for (int mt = 0; mt < 4; mt++)
#pragma unroll
        for (int nt = 0; nt < 4; nt++)
#pragma unroll
            for (int i = 0; i < 4; i++) acc[mt][nt][i] = 0.f;

    auto fill = [&](int kc, int st) {
        const uint32_t base = sb + st * PSTG;
        const int k0 = kc << 6;
#pragma unroll
        for (int j = 0; j < 4; j++) {
            const int g = tid + j * 256;
            const int row = g >> 3, q = g & 7;
            cpa16(base + row * 144 + q * 16,
                  d.A + (size_t)(bm * 128 + row) * d.K + k0 + q * 8);
            cpa16(base + 18432 + row * 144 + q * 16,
                  d.B + (size_t)(bn * 128 + row) * d.K + k0 + q * 8);
        }
    };

    fill(0, 0);
    asm volatile("cp.async.commit_group;" ::: "memory");
    fill(1, 1);
    asm volatile("cp.async.commit_group;" ::: "memory");

    int st = 0, stF = 2;
    for (int k = 0; k < NK; k++) {
        asm volatile("cp.async.wait_group 1;" ::: "memory");
        __syncthreads();

        if (k + 2 < NK) fill(k + 2, stF);
        asm volatile("cp.async.commit_group;" ::: "memory");

        const uint32_t* Ah = (const uint32_t*)(smem + st * PSTG);
        const uint32_t* Bh = (const uint32_t*)(smem + st * PSTG + 18432);
#pragma unroll
        for (int ks = 0; ks < 4; ks++) {
            const int kw = ks * 8 + (l & 3);
            uint32_t a[4][4];
#pragma unroll
            for (int mt = 0; mt < 4; mt++) {
                const int r = wm * 64 + mt * 16 + (l >> 2);
                a[mt][0] = Ah[r * LDW + kw];
                a[mt][1] = Ah[(r + 8) * LDW + kw];
                a[mt][2] = Ah[r * LDW + kw + 4];
                a[mt][3] = Ah[(r + 8) * LDW + kw + 4];
            }
#pragma unroll
            for (int nt = 0; nt < 4; nt++) {
                const int n = wn * 32 + nt * 8 + (l >> 2);
                uint32_t b[2];
                b[0] = Bh[n * LDW + kw];
                b[1] = Bh[n * LDW + kw + 4];
#pragma unroll
                for (int mt = 0; mt < 4; mt++) mma_f16(acc[mt][nt], a[mt], b);
            }
        }
        st++; if (st == 3) st = 0;
        stF++; if (stF == 3) stF = 0;
    }

#pragma unroll
    for (int mt = 0; mt < 4; mt++) {
        const int r0 = bm * 128 + wm * 64 + mt * 16 + (l >> 2);
#pragma unroll
        for (int nt = 0; nt < 4; nt++) {
            const int c0 = bn * 128 + wn * 32 + nt * 8 + 2 * (l & 3);
#pragma unroll
            for (int h = 0; h < 2; h++) {
                float vx = acc[mt][nt][2 * h + 0] * d.scale;
                float vy = acc[mt][nt][2 * h + 1] * d.scale;
                if (d.lrelu) {
                    vx = (vx >= 0.f) ? vx : 0.01f * vx;
                    vy = (vy >= 0.f) ? vy : 0.01f * vy;
                }
                if (EPIH) {
                    *(uint32_t*)((__half*)d.C + (size_t)(r0 + h * 8) * d.ldc + c0) =
                        pk(__float2half(vx), __float2half(vy));
                } else {
                    float2 v; v.x = vx; v.y = vy;
                    *(float2*)((float*)d.C + (size_t)(r0 + h * 8) * d.ldc + c0) = v;
                }
            }
        }
    }
}

__global__ void __launch_bounds__(256, 2)
mega2(PD d0, PD d1) {
    extern __shared__ char smem[];
    if (blockIdx.x < 256) gemm_p_body<1>(d0, blockIdx.x, smem);
    else gemm_p_body<1>(d1, blockIdx.x - 256, smem);
}
__global__ void __launch_bounds__(256, 2)
gemm_pf(PD d) {
    extern __shared__ char smem[];
    gemm_p_body<0>(d, blockIdx.x, smem);
}

// ---------------------------------------------------------------------------
// unified prep: one launch.
//   blocks [0,1024): tconv f1  (4096x256 -> [256,4096])
//   blocks [1024,1536): tconv f2
//   blocks [1536,2560): wconv W1+W2
//   blocks [2560,6656): gather feat[seed] -> Acat1[:,0:256)
// ---------------------------------------------------------------------------
__global__ void __launch_bounds__(256)
prep_all(const float* __restrict__ f1, const float* __restrict__ f2,
         const float* __restrict__ W1, const float* __restrict__ W2,
         const float4* __restrict__ feat, const int* __restrict__ seed,
         __half* __restrict__ f1h, __half* __restrict__ f2h,
         __half* __restrict__ Wh, __half* __restrict__ acat) {
    __shared__ float t[32][33];
    const int b = blockIdx.x;
    const int tx = threadIdx.x & 31, ty = threadIdx.x >> 5;   // (32,8)
    if (b < 1536) {
        // tconv: f1 tiles (128 x 8) then f2 tiles (64 x 8)
        const float* in; __half* o; int K, kb, nb;
        if (b < 1024) { in = f1; o = f1h; K = 4096; kb = b >> 3; nb = b & 7; }
        else { in = f2; o = f2h; K = 2048; kb = (b - 1024) >> 3; nb = (b - 1024) & 7; }
        const int k0 = kb * 32, n0 = nb * 32;
#pragma unroll
        for (int i = 0; i < 32; i += 8)
            t[ty + i][tx] = in[(size_t)(k0 + ty + i) * 256 + n0 + tx];
        __syncthreads();
#pragma unroll
        for (int i = 0; i < 32; i += 8)
            o[(size_t)(n0 + ty + i) * K + k0 + tx] = __float2half(t[tx][ty + i]);
    } else if (b < 2560) {
        const int i = (b - 1536) * 256 + threadIdx.x;
        if (i < 256 * 512) Wh[i] = __float2half(W1[i]);
        else Wh[i] = __float2half(W2[i - 256 * 512]);
    } else {
        const int g = (b - 2560) * 256 + threadIdx.x;        // 16384*64
        const int m = g >> 6, q = g & 63;
        float4 v = feat[(size_t)seed[m] * 64 + q];
        uint2 h;
        h.x = pk(__float2half(v.x), __float2half(v.y));
        h.y = pk(__float2half(v.z), __float2half(v.w));
        *(uint2*)(acat + (size_t)m * 512 + q * 4) = h;
    }
}

extern "C" void kernel_launch(void* const* d_in, const int* in_sizes, int n_in,
                              void* d_out, int out_size) {
    const float* feat = (const float*)d_in[0];
    const float* adj1 = (const float*)d_in[1];
    const float* f1 = (const float*)d_in[2];
    const float* adj2 = (const float*)d_in[3];
    const float* f2 = (const float*)d_in[4];
    const float* W1 = (const float*)d_in[5];
    const float* W2 = (const float*)d_in[6];
    const int* seed = (const int*)d_in[7];
    float* out = (float*)d_out;

    __half *A2h, *Acat1, *Acat2, *f1h, *f2h, *Wh;
    cudaGetSymbolAddress((void**)&A2h, g_A2h);
    cudaGetSymbolAddress((void**)&Acat1, g_Acat1);
    cudaGetSymbolAddress((void**)&Acat2, g_Acat2);
    cudaGetSymbolAddress((void**)&f1h, g_f1h);
    cudaGetSymbolAddress((void**)&f2h, g_f2h);
    cudaGetSymbolAddress((void**)&Wh, g_Wh);

    cudaFuncSetAttribute(gemm_f, cudaFuncAttributeMaxDynamicSharedMemorySize, SMEM_F);
    cudaFuncSetAttribute(mega2, cudaFuncAttributeMaxDynamicSharedMemorySize, SMEM_P);
    cudaFuncSetAttribute(gemm_pf, cudaFuncAttributeMaxDynamicSharedMemorySize, SMEM_P);

    // L1: all preps in one launch
    prep_all<<<6656, 256>>>(f1, f2, W1, W2, (const float4*)feat, seed,
                            f1h, f2h, Wh, Acat1);
    // L2: fold adj2 -> fp16 (full-chip streaming, no contention)
    fold4cvt<<<NFOLD, 256>>>(adj2, A2h);
    // L3: G1: Acat1[:,256:512) = fp16(0.5 * adj1 @ f1)
    gemm_f<<<dim3(2, 128), 256, SMEM_F>>>(adj1, f1h, Acat1 + 256);
    // L4: G2 || G3
    PD dG2 = {A2h, f2h, Acat2 + 256, 2048, 0.125f, 0, 512};
    PD dG3 = {Acat1, Wh, Acat2, 512, 1.0f, 1, 512};
    mega2<<<512, 256, SMEM_P>>>(dG2, dG3);
    // L5: G4 -> out (fp32)
    PD dG4 = {Acat2, Wh + 256 * 512, out, 512, 1.0f, 1, 256};
    gemm_pf<<<256, 256, SMEM_P>>>(dG4);
}

// round 15
// speedup vs baseline: 1.0408x; 1.0408x over previous
#include <cuda_runtime.h>
#include <cuda_fp16.h>
#include <cstdint>

// ============================================================================
// Gps, fp16 single-term mma.sync m16n8k16 (validated rel_err 4.400397e-4).
// R15: co-schedule G1 (latency-prone fused fp32-A GEMM) with G2 (tensor-bound
// pure-fp16 GEMM) in ONE launch — mega2's profile proved hetero GEMM pairs
// pack at the full-chip MMA floor. Chains: fold->G2, G1->G3, (G2,G3)->G4.
//   L1: prep_all   L2: fold4cvt   L3: mega(G1,G2)   L4: G3   L5: G4
// ============================================================================

#define ASTG 18432               // F: A stage 128 x 144B
#define OFFB 36864               // F: B stages at 36864 + st*18432 (3 stages)
#define PSTG 36864               // P: stage = A 18432 + B 18432
#define SMEM_P (3 * 36864)       // 110592 (covers F layout 92160 too)
#define LDW 36
#define NFOLD 1184

__device__ __half g_A2h[16384 * 2048];
__device__ __half g_Acat1[16384 * 512];
__device__ __half g_Acat2[16384 * 512];
__device__ __half g_f1h[256 * 4096];
__device__ __half g_f2h[256 * 2048];
__device__ __half g_Wh[2][256 * 512];

__device__ __forceinline__ uint32_t smem_u32(const void* p) {
    uint32_t a;
    asm("{ .reg .u64 t; cvta.to.shared.u64 t, %1; cvt.u32.u64 %0, t; }" : "=r"(a) : "l"(p));
    return a;
}
__device__ __forceinline__ void cpa16(uint32_t dst, const void* src) {
    asm volatile("cp.async.cg.shared.global [%0], [%1], 16;" :: "r"(dst), "l"(src));
}
__device__ __forceinline__ uint32_t pk(__half a, __half b) {
    __half2 t; t.x = a; t.y = b;
    return *(uint32_t*)&t;
}
__device__ __forceinline__ void mma_f16(float* c, const uint32_t* a, const uint32_t* b) {
    asm volatile(
        "mma.sync.aligned.m16n8k16.row.col.f32.f16.f16.f32 "
        "{%0,%1,%2,%3}, {%4,%5,%6,%7}, {%8,%9}, {%0,%1,%2,%3};"
        : "+f"(c[0]), "+f"(c[1]), "+f"(c[2]), "+f"(c[3])
        : "r"(a[0]), "r"(a[1]), "r"(a[2]), "r"(a[3]), "r"(b[0]), "r"(b[1]));
}

// ---------------------------------------------------------------------------
// G1 body: C_half[16384,256 @ldc 512] = fp16(0.5 * A_fp32[16384,4096] @ B^T)
// A: fused fp32 LDG->cvt->STS, 2 stages; B: cp.async, 3 stages.
// ---------------------------------------------------------------------------
__device__ __forceinline__ void gemm_f_body(
    const float* __restrict__ A, const __half* __restrict__ B,
    __half* __restrict__ C, int bidx, char* smem) {
    const uint32_t sb = smem_u32(smem);
    const int tid = threadIdx.x;
    const int l = tid & 31, wid = tid >> 5;
    const int wm = wid & 1, wn = wid >> 1;
    const int bn = bidx & 1, bm = bidx >> 1;
    const int NK = 64;

    float acc[4][4][4];
#pragma unroll
    for (int mt = 0; mt < 4; mt++)
#pragma unroll
        for (int nt = 0; nt < 4; nt++)
#pragma unroll
            for (int i = 0; i < 4; i++) acc[mt][nt][i] = 0.f;

    const int rbase = tid >> 4;
    const int kq = (tid & 15) << 2;

    auto ldgA = [&](int kc, int hb, float4* r) {
#pragma unroll
        for (int j = 0; j < 4; j++) {
            const int row = rbase + 16 * (hb * 4 + j);
            r[j] = *(const float4*)(A + (size_t)(bm * 128 + row) * 4096 +
                                    (kc << 6) + kq);
        }
    };
    auto stsA = [&](const float4* r, int hb, int s) {
        char* base = smem + s * ASTG;
        const int q = tid & 15;
#pragma unroll
        for (int j = 0; j < 4; j++) {
            const int row = rbase + 16 * (hb * 4 + j);
            uint2 h;
            h.x = pk(__float2half(r[j].x), __float2half(r[j].y));
            h.y = pk(__float2half(r[j].z), __float2half(r[j].w));
            *(uint2*)(base + row * 144 + q * 8) = h;
        }
    };
    auto fillB = [&](int kc, int st) {
#pragma unroll
        for (int j = 0; j < 4; j++) {
            const int g = tid + j * 256;
            const int row = g >> 3, q = g & 7;
            cpa16(sb + OFFB + st * ASTG + row * 144 + q * 16,
                  B + (size_t)(bn * 128 + row) * 4096 + (kc << 6) + q * 8);
        }
        asm volatile("cp.async.commit_group;" ::: "memory");
    };

    fillB(0, 0);
    fillB(1, 1);
    {
        float4 a0[4];
        ldgA(0, 0, a0); stsA(a0, 0, 0);
        ldgA(0, 1, a0); stsA(a0, 1, 0);
    }

    int stB = 0, stF = 2;
    for (int k = 0; k < NK; k++) {
        const int sA = k & 1;
        if (k < NK - 1) asm volatile("cp.async.wait_group 1;" ::: "memory");
        else            asm volatile("cp.async.wait_group 0;" ::: "memory");
        __syncthreads();

        if (k + 2 < NK) fillB(k + 2, stF);
        float4 ar[4];
        if (k + 1 < NK) ldgA(k + 1, 0, ar);

        const uint32_t* Ah = (const uint32_t*)(smem + sA * ASTG);
        const uint32_t* Bh = (const uint32_t*)(smem + OFFB + stB * ASTG);
#pragma unroll
        for (int half = 0; half < 2; half++) {
#pragma unroll
            for (int ki = 0; ki < 2; ki++) {
                const int ks = half * 2 + ki;
                const int kw = ks * 8 + (l & 3);
                uint32_t a[4][4];
#pragma unroll
                for (int mt = 0; mt < 4; mt++) {
                    const int r = wm * 64 + mt * 16 + (l >> 2);
                    a[mt][0] = Ah[r * LDW + kw];
                    a[mt][1] = Ah[(r + 8) * LDW + kw];
                    a[mt][2] = Ah[r * LDW + kw + 4];
                    a[mt][3] = Ah[(r + 8) * LDW + kw + 4];
                }
#pragma unroll
                for (int nt = 0; nt < 4; nt++) {
                    const int n = wn * 32 + nt * 8 + (l >> 2);
                    uint32_t b[2];
                    b[0] = Bh[n * LDW + kw];
                    b[1] = Bh[n * LDW + kw + 4];
#pragma unroll
                    for (int mt = 0; mt < 4; mt++) mma_f16(acc[mt][nt], a[mt], b);
                }
            }
            if (k + 1 < NK) {
                stsA(ar, half, sA ^ 1);
                if (half == 0) ldgA(k + 1, 1, ar);
            }
        }
        stB++; if (stB == 3) stB = 0;
        stF++; if (stF == 3) stF = 0;
    }

#pragma unroll
    for (int mt = 0; mt < 4; mt++) {
        const int r0 = bm * 128 + wm * 64 + mt * 16 + (l >> 2);
#pragma unroll
        for (int nt = 0; nt < 4; nt++) {
            const int c0 = bn * 128 + wn * 32 + nt * 8 + 2 * (l & 3);
#pragma unroll
            for (int h = 0; h < 2; h++) {
                const float vx = acc[mt][nt][2 * h + 0] * 0.5f;
                const float vy = acc[mt][nt][2 * h + 1] * 0.5f;
                *(uint32_t*)(C + (size_t)(r0 + h * 8) * 512 + c0) =
                    pk(__float2half(vx), __float2half(vy));
            }
        }
    }
}

// ---------------------------------------------------------------------------
// P body: pure-fp16 GEMM, both operands cp.async, 3 stages, K-chunk 64.
// ---------------------------------------------------------------------------
struct PD {
    const __half* A; const __half* B; void* C;
    int K; float scale; int lrelu; int ldc;
};

template <int EPIH>
__device__ __forceinline__ void gemm_p_body(const PD d, int bidx, char* smem) {
    const uint32_t sb = smem_u32(smem);
    const int tid = threadIdx.x;
    const int l = tid & 31, wid = tid >> 5;
    const int wm = wid & 1, wn = wid >> 1;
    const int bn = bidx & 1, bm = bidx >> 1;
    const int NK = d.K >> 6;

    float acc[4][4][4];
#pragma unroll
    for (int mt = 0; mt < 4; mt++)
#pragma unroll
        for (int nt = 0; nt < 4; nt++)
#pragma unroll
            for (int i = 0; i < 4; i++) acc[mt][nt][i] = 0.f;

    auto fill = [&](int kc, int st) {
        const uint32_t base = sb + st * PSTG;
        const int k0 = kc << 6;
#pragma unroll
        for (int j = 0; j < 4; j++) {
            const int g = tid + j * 256;
            const int row = g >> 3, q = g & 7;
            cpa16(base + row * 144 + q * 16,
                  d.A + (size_t)(bm * 128 + row) * d.K + k0 + q * 8);
            cpa16(base + 18432 + row * 144 + q * 16,
                  d.B + (size_t)(bn * 128 + row) * d.K + k0 + q * 8);
        }
    };

    fill(0, 0);
    asm volatile("cp.async.commit_group;" ::: "memory");
    fill(1, 1);
    asm volatile("cp.async.commit_group;" ::: "memory");

    int st = 0, stF = 2;
    for (int k = 0; k < NK; k++) {
        asm volatile("cp.async.wait_group 1;" ::: "memory");
        __syncthreads();

        if (k + 2 < NK) fill(k + 2, stF);
        asm volatile("cp.async.commit_group;" ::: "memory");

        const uint32_t* Ah = (const uint32_t*)(smem + st * PSTG);
        const uint32_t* Bh = (const uint32_t*)(smem + st * PSTG + 18432);
#pragma unroll
        for (int ks = 0; ks < 4; ks++) {
            const int kw = ks * 8 + (l & 3);
            uint32_t a[4][4];
#pragma unroll
            for (int mt = 0; mt < 4; mt++) {
                const int r = wm * 64 + mt * 16 + (l >> 2);
                a[mt][0] = Ah[r * LDW + kw];
                a[mt][1] = Ah[(r + 8) * LDW + kw];
                a[mt][2] = Ah[r * LDW + kw + 4];
                a[mt][3] = Ah[(r + 8) * LDW + kw + 4];
            }
#pragma unroll
            for (int nt = 0; nt < 4; nt++) {
                const int n = wn * 32 + nt * 8 + (l >> 2);
                uint32_t b[2];
                b[0] = Bh[n * LDW + kw];
                b[1] = Bh[n * LDW + kw + 4];
#pragma unroll
                for (int mt = 0; mt < 4; mt++) mma_f16(acc[mt][nt], a[mt], b);
            }
        }
        st++; if (st == 3) st = 0;
        stF++; if (stF == 3) stF = 0;
    }

#pragma unroll
    for (int mt = 0; mt < 4; mt++) {
        const int r0 = bm * 128 + wm * 64 + mt * 16 + (l >> 2);
#pragma unroll
        for (int nt = 0; nt < 4; nt++) {
            const int c0 = bn * 128 + wn * 32 + nt * 8 + 2 * (l & 3);
#pragma unroll
            for (int h = 0; h < 2; h++) {
                float vx = acc[mt][nt][2 * h + 0] * d.scale;
                float vy = acc[mt][nt][2 * h + 1] * d.scale;
                if (d.lrelu) {
                    vx = (vx >= 0.f) ? vx : 0.01f * vx;
                    vy = (vy >= 0.f) ? vy : 0.01f * vy;
                }
                if (EPIH) {
                    *(uint32_t*)((__half*)d.C + (size_t)(r0 + h * 8) * d.ldc + c0) =
                        pk(__float2half(vx), __float2half(vy));
                } else {
                    float2 v; v.x = vx; v.y = vy;
                    *(float2*)((float*)d.C + (size_t)(r0 + h * 8) * d.ldc + c0) = v;
                }
            }
        }
    }
}

// mega: blocks [0,256) = G1 (long pole, starts first), [256,512) = G2
__global__ void __launch_bounds__(256, 2)
mega_g12(const float* __restrict__ adj1, const __half* __restrict__ f1h,
         __half* __restrict__ C1, PD dG2) {
    extern __shared__ char smem[];
    if (blockIdx.x < 256) gemm_f_body(adj1, f1h, C1, blockIdx.x, smem);
    else gemm_p_body<1>(dG2, blockIdx.x - 256, smem);
}
__global__ void __launch_bounds__(256, 2)
gemm_ph(PD d) {
    extern __shared__ char smem[];
    gemm_p_body<1>(d, blockIdx.x, smem);
}
__global__ void __launch_bounds__(256, 2)
gemm_pf(PD d) {
    extern __shared__ char smem[];
    gemm_p_body<0>(d, blockIdx.x, smem);
}

// ---------------------------------------------------------------------------
// fold4cvt: A2h[m][k] = fp16(sum_{i<4} adj2[4m+i][k]); full-chip streaming.
// ---------------------------------------------------------------------------
__global__ void __launch_bounds__(256)
fold4cvt(const float* __restrict__ in, __half* __restrict__ out) {
    const int T = NFOLD * 256;
    const int idx = blockIdx.x * 256 + threadIdx.x;
    const int NJ = 16384 * 512;
    for (int j0 = idx; j0 < NJ; j0 += 4 * T) {
        float4 v[4][4];
        int jj[4];
#pragma unroll
        for (int u = 0; u < 4; u++) {
            jj[u] = j0 + u * T;
            if (jj[u] < NJ) {
                const int m = jj[u] >> 9, k4 = (jj[u] & 511) << 2;
                const float* p = in + (size_t)m * 4 * 2048 + k4;
                v[u][0] = *(const float4*)p;
                v[u][1] = *(const float4*)(p + 2048);
                v[u][2] = *(const float4*)(p + 4096);
                v[u][3] = *(const float4*)(p + 6144);
            }
        }
#pragma unroll
        for (int u = 0; u < 4; u++) {
            if (jj[u] < NJ) {
                const int m = jj[u] >> 9, k4 = (jj[u] & 511) << 2;
                uint2 h;
                h.x = pk(__float2half((v[u][0].x + v[u][1].x) + (v[u][2].x + v[u][3].x)),
                         __float2half((v[u][0].y + v[u][1].y) + (v[u][2].y + v[u][3].y)));
                h.y = pk(__float2half((v[u][0].z + v[u][1].z) + (v[u][2].z + v[u][3].z)),
                         __float2half((v[u][0].w + v[u][1].w) + (v[u][2].w + v[u][3].w)));
                *(uint2*)(out + (size_t)m * 2048 + k4) = h;
            }
        }
    }
}

// ---------------------------------------------------------------------------
// unified prep (one launch): tconv f1, tconv f2, wconv W1/W2, gather.
// ---------------------------------------------------------------------------
__global__ void __launch_bounds__(256)
prep_all(const float* __restrict__ f1, const float* __restrict__ f2,
         const float* __restrict__ W1, const float* __restrict__ W2,
         const float4* __restrict__ feat, const int* __restrict__ seed,
         __half* __restrict__ f1h, __half* __restrict__ f2h,
         __half* __restrict__ Wh, __half* __restrict__ acat) {
    __shared__ float t[32][33];
    const int b = blockIdx.x;
    const int tx = threadIdx.x & 31, ty = threadIdx.x >> 5;
    if (b < 1536) {
        const float* in; __half* o; int K, kb, nb;
        if (b < 1024) { in = f1; o = f1h; K = 4096; kb = b >> 3; nb = b & 7; }
        else { in = f2; o = f2h; K = 2048; kb = (b - 1024) >> 3; nb = (b - 1024) & 7; }
        const int k0 = kb * 32, n0 = nb * 32;
#pragma unroll
        for (int i = 0; i < 32; i += 8)
            t[ty + i][tx] = in[(size_t)(k0 + ty + i) * 256 + n0 + tx];
        __syncthreads();
#pragma unroll
        for (int i = 0; i < 32; i += 8)
            o[(size_t)(n0 + ty + i) * K + k0 + tx] = __float2half(t[tx][ty + i]);
    } else if (b < 2560) {
        const int i = (b - 1536) * 256 + threadIdx.x;
        if (i < 256 * 512) Wh[i] = __float2half(W1[i]);
        else Wh[i] = __float2half(W2[i - 256 * 512]);
    } else {
        const int g = (b - 2560) * 256 + threadIdx.x;
        const int m = g >> 6, q = g & 63;
        float4 v = feat[(size_t)seed[m] * 64 + q];
        uint2 h;
        h.x = pk(__float2half(v.x), __float2half(v.y));
        h.y = pk(__float2half(v.z), __float2half(v.w));
        *(uint2*)(acat + (size_t)m * 512 + q * 4) = h;
    }
}

extern "C" void kernel_launch(void* const* d_in, const int* in_sizes, int n_in,
                              void* d_out, int out_size) {
    const float* feat = (const float*)d_in[0];
    const float* adj1 = (const float*)d_in[1];
    const float* f1 = (const float*)d_in[2];
    const float* adj2 = (const float*)d_in[3];
    const float* f2 = (const float*)d_in[4];
    const float* W1 = (const float*)d_in[5];
    const float* W2 = (const float*)d_in[6];
    const int* seed = (const int*)d_in[7];
    float* out = (float*)d_out;

    __half *A2h, *Acat1, *Acat2, *f1h, *f2h, *Wh;
    cudaGetSymbolAddress((void**)&A2h, g_A2h);
    cudaGetSymbolAddress((void**)&Acat1, g_Acat1);
    cudaGetSymbolAddress((void**)&Acat2, g_Acat2);
    cudaGetSymbolAddress((void**)&f1h, g_f1h);
    cudaGetSymbolAddress((void**)&f2h, g_f2h);
    cudaGetSymbolAddress((void**)&Wh, g_Wh);

    cudaFuncSetAttribute(mega_g12, cudaFuncAttributeMaxDynamicSharedMemorySize, SMEM_P);
    cudaFuncSetAttribute(gemm_ph, cudaFuncAttributeMaxDynamicSharedMemorySize, SMEM_P);
    cudaFuncSetAttribute(gemm_pf, cudaFuncAttributeMaxDynamicSharedMemorySize, SMEM_P);

    // L1: all preps
    prep_all<<<6656, 256>>>(f1, f2, W1, W2, (const float4*)feat, seed,
                            f1h, f2h, Wh, Acat1);
    // L2: fold adj2 -> fp16 (solo: streaming, must not co-run with G1)
    fold4cvt<<<NFOLD, 256>>>(adj2, A2h);
    // L3: G1 + G2 co-scheduled (fills all 296 CTA slots; G2 MMAs hide G1 stalls)
    PD dG2 = {A2h, f2h, Acat2 + 256, 2048, 0.125f, 0, 512};
    mega_g12<<<512, 256, SMEM_P>>>(adj1, f1h, Acat1 + 256, dG2);
    // L4: G3: Acat2[:,0:256) = fp16(lrelu(Acat1 @ W1^T))
    PD dG3 = {Acat1, Wh, Acat2, 512, 1.0f, 1, 512};
    gemm_ph<<<256, 256, SMEM_P>>>(dG3);
    // L5: G4 -> out (fp32)
    PD dG4 = {Acat2, Wh + 256 * 512, out, 512, 1.0f, 1, 256};
    gemm_pf<<<256, 256, SMEM_P>>>(dG4);
}